// round 1
// baseline (speedup 1.0000x reference)
#include <cuda_runtime.h>

#define NPIX  (1024*1024)
#define TPB   512
#define NWARP (TPB/32)
#define NCTA  148
#define PPC   7085            // ceil(NPIX / NCTA)
#define EPSF  1e-8f
#define NITER 100

// ---------------- device globals (scratch; zeroed each launch by hx_init) ----
__device__ unsigned g_bar;                 // grid barrier arrival counter
__device__ unsigned g_h0[2048];            // radix-select histograms
__device__ unsigned g_h1[2048];
__device__ unsigned g_h2[1024];
__device__ float    g_part[2][22 * 160];   // per-CTA reduction partials, parity double-buffered

__global__ void hx_init() {
    int t = blockIdx.x * blockDim.x + threadIdx.x;
    if (t == 0) g_bar = 0u;
    if (t < 2048) { g_h0[t] = 0u; g_h1[t] = 0u; }
    if (t < 1024) g_h2[t] = 0u;
}

// ---------------- software grid barrier (all 148 CTAs co-resident) ----------
__device__ __forceinline__ void gsync(unsigned target) {
    __syncthreads();
    if (threadIdx.x == 0) {
        __threadfence();                       // release prior global writes
        atomicAdd(&g_bar, 1u);
        while (*(volatile unsigned*)&g_bar < target) { }
        __threadfence();
    }
    __syncthreads();
}

// ---------------- warp-0 bin search for radix select -----------------------
// Finds bin b s.t. cum[0..b) <= r < cum[0..b]; writes {bin, count_before} to sel_out.
__device__ __forceinline__ void find_bin(const unsigned* hist, int nb, unsigned r,
                                         unsigned* sel_out) {
    int lane = threadIdx.x & 31;
    int ch = nb >> 5;
    unsigned csum = 0;
    for (int i = 0; i < ch; ++i) csum += __ldcg(&hist[lane * ch + i]);
    unsigned inc = csum;
#pragma unroll
    for (int off = 1; off < 32; off <<= 1) {
        unsigned t = __shfl_up_sync(0xffffffffu, inc, off);
        if (lane >= off) inc += t;
    }
    unsigned excl = inc - csum;
    bool has = (r >= excl) && (r < inc);
    unsigned m = __ballot_sync(0xffffffffu, has);
    int sel = __ffs(m) - 1;
    unsigned bin = 0, before = 0;
    if (lane == sel) {
        unsigned c = excl;
        for (int i = 0; i < ch; ++i) {
            unsigned h = __ldcg(&hist[sel * ch + i]);
            if (r < c + h) { bin = (unsigned)(sel * ch + i); before = c; break; }
            c += h;
        }
    }
    bin    = __shfl_sync(0xffffffffu, bin, sel);
    before = __shfl_sync(0xffffffffu, before, sel);
    if (lane == 0) { sel_out[0] = bin; sel_out[1] = before; }
}

// ---------------- the persistent kernel -------------------------------------
__global__ void __launch_bounds__(TPB, 1)
he_norm_kernel(const float* __restrict__ pic, const float* __restrict__ Wt,
               const float* __restrict__ HtRM, const float* __restrict__ W0,
               const float* __restrict__ H0, float* __restrict__ out) {
    extern __shared__ float smem[];
    float4*   sW    = (float4*)smem;                     // PPC * 16 B
    float*    sV    = smem + 4 * PPC;                    // 3 * PPC * 4 B
    unsigned* sHist = (unsigned*)(sV + 3 * PPC);         // 2048 * 4 B
    float*    sRed  = (float*)(sHist + 2048);            // NWARP * 22 floats
    float*    sB    = sRed + NWARP * 22;                 // 24 floats broadcast
    unsigned* sSel  = (unsigned*)(sB + 24);              // 2 u32

    const int tid  = threadIdx.x;
    const int cta  = blockIdx.x;
    const int base = cta * PPC;
    const int cnt  = min(PPC, NPIX - base);

    // ---- prologue: load W0 slice and compute V = -log(clip(pic)) into smem
    const float4* W0v = (const float4*)W0;
    for (int p = tid; p < cnt; p += TPB) sW[p] = W0v[base + p];
    for (int c = 0; c < 3; ++c)
        for (int p = tid; p < cnt; p += TPB) {
            float x = pic[c * NPIX + base + p];
            x = fminf(fmaxf(x, 0.01f), 0.99f);
            sV[c * PPC + p] = -__logf(x);
        }
    float Hd[12];
#pragma unroll
    for (int i = 0; i < 12; ++i) Hd[i] = H0[i];
    __syncthreads();

    unsigned nsync = 0;

    // ---- NMF multiplicative updates --------------------------------------
    for (int it = 0; it < NITER; ++it) {
        // Gram G = Hd^T Hd (4x4), replicated per thread
        float G[16];
#pragma unroll
        for (int k = 0; k < 4; ++k)
#pragma unroll
            for (int j = 0; j < 4; ++j)
                G[k * 4 + j] = Hd[k] * Hd[j] + Hd[4 + k] * Hd[4 + j] + Hd[8 + k] * Hd[8 + j];

        float acc[22];
#pragma unroll
        for (int i = 0; i < 22; ++i) acc[i] = 0.f;

        for (int p = tid; p < cnt; p += TPB) {
            float4 w = sW[p];
            float v0 = sV[p], v1 = sV[PPC + p], v2 = sV[2 * PPC + p];
            // t[j] = (V^T Hd)[pixel][j]
            float t0 = v0 * Hd[0] + v1 * Hd[4] + v2 * Hd[8];
            float t1 = v0 * Hd[1] + v1 * Hd[5] + v2 * Hd[9];
            float t2 = v0 * Hd[2] + v1 * Hd[6] + v2 * Hd[10];
            float t3 = v0 * Hd[3] + v1 * Hd[7] + v2 * Hd[11];
            // d[j] = (Wc G)[pixel][j]
            float d0 = w.x * G[0] + w.y * G[4] + w.z * G[8]  + w.w * G[12];
            float d1 = w.x * G[1] + w.y * G[5] + w.z * G[9]  + w.w * G[13];
            float d2 = w.x * G[2] + w.y * G[6] + w.z * G[10] + w.w * G[14];
            float d3 = w.x * G[3] + w.y * G[7] + w.z * G[11] + w.w * G[15];
            float n0 = __fdividef(w.x * t0, d0 + EPSF);
            float n1 = __fdividef(w.y * t1, d1 + EPSF);
            float n2 = __fdividef(w.z * t2, d2 + EPSF);
            float n3 = __fdividef(w.w * t3, d3 + EPSF);
            sW[p] = make_float4(n0, n1, n2, n3);
            // S1 = V @ Wc_new (3x4)
            acc[0]  += v0 * n0; acc[1]  += v0 * n1; acc[2]  += v0 * n2; acc[3]  += v0 * n3;
            acc[4]  += v1 * n0; acc[5]  += v1 * n1; acc[6]  += v1 * n2; acc[7]  += v1 * n3;
            acc[8]  += v2 * n0; acc[9]  += v2 * n1; acc[10] += v2 * n2; acc[11] += v2 * n3;
            // S2 = Wc_new^T Wc_new (sym, 10 uniques)
            acc[12] += n0 * n0; acc[13] += n0 * n1; acc[14] += n0 * n2; acc[15] += n0 * n3;
            acc[16] += n1 * n1; acc[17] += n1 * n2; acc[18] += n1 * n3;
            acc[19] += n2 * n2; acc[20] += n2 * n3; acc[21] += n3 * n3;
        }

        if (it == NITER - 1) break;   // final Hd update is dead work

        // block reduce 22 accumulators
#pragma unroll
        for (int i = 0; i < 22; ++i) {
            float v = acc[i];
#pragma unroll
            for (int off = 16; off > 0; off >>= 1) v += __shfl_down_sync(0xffffffffu, v, off);
            acc[i] = v;
        }
        int lane = tid & 31, warp = tid >> 5;
        if (lane == 0) {
#pragma unroll
            for (int i = 0; i < 22; ++i) sRed[warp * 22 + i] = acc[i];
        }
        __syncthreads();
        const int par = it & 1;
        if (tid < 22) {
            float s = 0.f;
#pragma unroll
            for (int w = 0; w < NWARP; ++w) s += sRed[w * 22 + tid];
            g_part[par][tid * 160 + cta] = s;
        }
        gsync(++nsync * NCTA);
        if (tid < 22) {
            float s = 0.f;
            for (int i = 0; i < NCTA; ++i) s += __ldcg(&g_part[par][tid * 160 + i]);
            sB[tid] = s;
        }
        __syncthreads();

        // Hd update (redundant, deterministic in every thread)
        float S2[16];
        {
            float p00 = sB[12], p01 = sB[13], p02 = sB[14], p03 = sB[15];
            float p11 = sB[16], p12 = sB[17], p13 = sB[18];
            float p22 = sB[19], p23 = sB[20], p33 = sB[21];
            S2[0]=p00; S2[1]=p01; S2[2]=p02; S2[3]=p03;
            S2[4]=p01; S2[5]=p11; S2[6]=p12; S2[7]=p13;
            S2[8]=p02; S2[9]=p12; S2[10]=p22; S2[11]=p23;
            S2[12]=p03; S2[13]=p13; S2[14]=p23; S2[15]=p33;
        }
        float Hn[12];
#pragma unroll
        for (int c = 0; c < 3; ++c)
#pragma unroll
            for (int j = 0; j < 4; ++j) {
                float den = Hd[c*4+0]*S2[0*4+j] + Hd[c*4+1]*S2[1*4+j]
                          + Hd[c*4+2]*S2[2*4+j] + Hd[c*4+3]*S2[3*4+j] + EPSF;
                Hn[c*4+j] = __fdividef(Hd[c*4+j] * sB[c*4+j], den);
            }
#pragma unroll
        for (int i = 0; i < 12; ++i) Hd[i] = Hn[i];
    }

    // ---- global 0.99-quantile over 4N Wc values: 3-round radix select ------
    // jnp: idx = 0.99f*(4N-1) in f32 == exactly 4152360.0 -> single order stat.
    float pos = 0.99f * (float)(4 * NPIX - 1);
    unsigned lo = (unsigned)pos;
    float fr = pos - (float)lo;
    unsigned rank = lo + (fr > 0.5f ? 1u : 0u);

    const float* wf = (const float*)sW;
    const int tot = cnt * 4;
    unsigned b0, b1, b2;

    // round 0: bits [31:21]
    for (int i = tid; i < 2048; i += TPB) sHist[i] = 0u;
    __syncthreads();
    for (int i = tid; i < tot; i += TPB) {
        unsigned k = __float_as_uint(wf[i]);
        atomicAdd(&sHist[k >> 21], 1u);
    }
    __syncthreads();
    for (int i = tid; i < 2048; i += TPB) { unsigned h = sHist[i]; if (h) atomicAdd(&g_h0[i], h); }
    gsync(++nsync * NCTA);
    if (tid < 32) find_bin(g_h0, 2048, rank, sSel);
    __syncthreads();
    b0 = sSel[0]; rank -= sSel[1];

    // round 1: bits [20:10]
    for (int i = tid; i < 2048; i += TPB) sHist[i] = 0u;
    __syncthreads();
    for (int i = tid; i < tot; i += TPB) {
        unsigned k = __float_as_uint(wf[i]);
        if ((k >> 21) == b0) atomicAdd(&sHist[(k >> 10) & 2047u], 1u);
    }
    __syncthreads();
    for (int i = tid; i < 2048; i += TPB) { unsigned h = sHist[i]; if (h) atomicAdd(&g_h1[i], h); }
    gsync(++nsync * NCTA);
    if (tid < 32) find_bin(g_h1, 2048, rank, sSel);
    __syncthreads();
    b1 = sSel[0]; rank -= sSel[1];

    // round 2: bits [9:0]
    for (int i = tid; i < 1024; i += TPB) sHist[i] = 0u;
    __syncthreads();
    unsigned pref = (b0 << 11) | b1;
    for (int i = tid; i < tot; i += TPB) {
        unsigned k = __float_as_uint(wf[i]);
        if ((k >> 10) == pref) atomicAdd(&sHist[k & 1023u], 1u);
    }
    __syncthreads();
    for (int i = tid; i < 1024; i += TPB) { unsigned h = sHist[i]; if (h) atomicAdd(&g_h2[i], h); }
    gsync(++nsync * NCTA);
    if (tid < 32) find_bin(g_h2, 1024, rank, sSel);
    __syncthreads();
    b2 = sSel[0];

    float qv = __uint_as_float((b0 << 21) | (b1 << 10) | b2);

    // ---- epilogue: out = clip(exp(-(W_target @ (Wc^T * Ht/q))), 0, 1) -------
    float s = HtRM[0] / qv;
    float w0 = Wt[0]*s,  w1 = Wt[1]*s,  w2 = Wt[2]*s,  w3 = Wt[3]*s;
    float w4 = Wt[4]*s,  w5 = Wt[5]*s,  w6 = Wt[6]*s,  w7 = Wt[7]*s;
    float w8 = Wt[8]*s,  w9 = Wt[9]*s,  wA = Wt[10]*s, wB = Wt[11]*s;
    for (int p = tid; p < cnt; p += TPB) {
        float4 w = sW[p];
        float a0 = w0*w.x + w1*w.y + w2*w.z + w3*w.w;
        float a1 = w4*w.x + w5*w.y + w6*w.z + w7*w.w;
        float a2 = w8*w.x + w9*w.y + wA*w.z + wB*w.w;
        out[0*NPIX + base + p] = __saturatef(__expf(-a0));
        out[1*NPIX + base + p] = __saturatef(__expf(-a1));
        out[2*NPIX + base + p] = __saturatef(__expf(-a2));
    }
}

// ---------------- launch ----------------------------------------------------
extern "C" void kernel_launch(void* const* d_in, const int* in_sizes, int n_in,
                              void* d_out, int out_size) {
    const float *pic = nullptr, *Wt = nullptr, *Htq = nullptr, *W0 = nullptr, *H0 = nullptr;
    for (int i = 0; i < n_in; ++i) {
        int sz = in_sizes[i];
        if      (sz == 3 * NPIX) pic = (const float*)d_in[i];
        else if (sz == 4 * NPIX) W0  = (const float*)d_in[i];
        else if (sz == 1)        Htq = (const float*)d_in[i];
        else if (sz == 12) { if (!Wt) Wt = (const float*)d_in[i]; else H0 = (const float*)d_in[i]; }
    }
    float* out = (float*)d_out;

    const size_t smem_bytes =
        (size_t)PPC * 16 +            // sW
        (size_t)PPC * 12 +            // sV
        2048 * 4 +                    // sHist
        NWARP * 22 * 4 +              // sRed
        24 * 4 + 2 * 4 + 64;          // sB + sSel + pad

    cudaFuncSetAttribute(he_norm_kernel, cudaFuncAttributeMaxDynamicSharedMemorySize,
                         (int)smem_bytes);

    hx_init<<<4, 512>>>();
    he_norm_kernel<<<NCTA, TPB, smem_bytes>>>(pic, Wt, Htq, W0, H0, out);
}